// round 4
// baseline (speedup 1.0000x reference)
#include <cuda_runtime.h>
#include <cuda_bf16.h>

// Problem constants
#define NN   20000
#define EE   320000
#define FIN  128
#define HID  64
#define HC   256   // H*C
#define LL   4

// ---------------- scratch (device globals; no allocation allowed) ----------------
__device__ __align__(16) float g_h   [NN*HID];
__device__ __align__(16) float g_z   [NN*HID];
__device__ __align__(16) float g_skip[NN*HID];
__device__ __align__(16) float g_A1  [NN*HID];
__device__ __align__(16) float g_q   [NN*HC];
__device__ __align__(16) float g_k   [NN*HC];
__device__ __align__(16) float g_v   [NN*HC];
__device__ __align__(16) float g_p   [NN*HC];
__device__ __align__(16) float g_R   [NN*HC];
__device__ __align__(16) float g_ea  [EE*HID];
__device__ __align__(16) float g_eas [EE*HID];
__device__ __align__(16) float g_Wp  [LL*HID*HC];
__device__ __align__(16) float g_bp  [LL*HC];
__device__ __align__(16) float g_M   [LL*HC*HID];
__device__ int g_deg [NN];
__device__ int g_off [NN+1];
__device__ int g_cur [NN];
__device__ int g_csrc[EE];
__device__ int g_ceid[EE];

// ---------------- small utility kernels ----------------
__global__ void zero_int_kernel(int* p, int n) {
    int i = blockIdx.x * blockDim.x + threadIdx.x;
    if (i < n) p[i] = 0;
}

__global__ void hist_kernel(const int* __restrict__ ei, int* __restrict__ deg, int E) {
    int e = blockIdx.x * blockDim.x + threadIdx.x;
    if (e < E) atomicAdd(&deg[ei[E + e]], 1);
}

// single-block exclusive scan of deg -> off, cur  (n = 20000, 1024 threads)
__global__ void scan_kernel(const int* __restrict__ deg, int* __restrict__ off,
                            int* __restrict__ cur, int n, int total) {
    const int T = 1024;
    int tid = threadIdx.x;
    int chunk = (n + T - 1) / T;
    int s = tid * chunk;
    int e = s + chunk; if (e > n) e = n;
    int local = 0;
    for (int i = s; i < e; i++) local += deg[i];
    int lane = tid & 31, w = tid >> 5;
    int v = local;
    #pragma unroll
    for (int o = 1; o < 32; o <<= 1) {
        int t2 = __shfl_up_sync(0xffffffffu, v, o);
        if (lane >= o) v += t2;
    }
    __shared__ int wsum[32];
    if (lane == 31) wsum[w] = v;
    __syncthreads();
    if (w == 0) {
        int x = wsum[lane];
        #pragma unroll
        for (int o = 1; o < 32; o <<= 1) {
            int t2 = __shfl_up_sync(0xffffffffu, x, o);
            if (lane >= o) x += t2;
        }
        wsum[lane] = x;
    }
    __syncthreads();
    int incl = v + (w > 0 ? wsum[w - 1] : 0);
    int p = incl - local;   // exclusive prefix
    for (int i = s; i < e; i++) { off[i] = p; cur[i] = p; p += deg[i]; }
    if (tid == 0) off[n] = total;
}

__global__ void scatter_kernel(const int* __restrict__ ei, int* __restrict__ cur,
                               int* __restrict__ csrc, int* __restrict__ ceid, int E) {
    int e = blockIdx.x * blockDim.x + threadIdx.x;
    if (e >= E) return;
    int s = ei[e];
    int d = ei[E + e];
    int pos = atomicAdd(&cur[d], 1);
    csrc[pos] = s;
    ceid[pos] = e;
}

// permute encoded edge features into CSR order: eas[pos] = ea[ceid[pos]]
__global__ void permute_ea_kernel(const float* __restrict__ ea, const int* __restrict__ ceid,
                                  float* __restrict__ eas, int E) {
    int idx = blockIdx.x * blockDim.x + threadIdx.x;
    if (idx >= E * 16) return;
    int pos = idx >> 4;
    int q4 = idx & 15;
    int eid = ceid[pos];
    reinterpret_cast<float4*>(eas + (size_t)pos * 64)[q4] =
        reinterpret_cast<const float4*>(ea + (size_t)eid * 64)[q4];
}

// ---------------- weight prep ----------------
// Wp[l][f][h*64+j] = sum_c Wq[l][f][h*64+c] * We[l][j][h*64+c]   (f==64 row -> bp from bq)
__global__ void prep_wp_kernel(const float* __restrict__ Wq, const float* __restrict__ bq,
                               const float* __restrict__ We,
                               float* __restrict__ Wp, float* __restrict__ bp) {
    int idx = blockIdx.x * blockDim.x + threadIdx.x;
    if (idx >= LL * 65 * HC) return;
    int hj = idx & 255;
    int t = idx >> 8;
    int f = t % 65;
    int l = t / 65;
    int h = hj >> 6, j = hj & 63;
    const float* arow = (f < 64) ? (Wq + l * HID * HC + f * HC) : (bq + l * HC);
    const float* wrow = We + l * HID * HC + j * HC;
    float s = 0.f;
    #pragma unroll 8
    for (int c = 0; c < 64; c++) s += arow[h * 64 + c] * wrow[h * 64 + c];
    if (f < 64) Wp[l * HID * HC + f * HC + hj] = s;
    else        bp[l * HC + hj] = s;
}

// M[l][h*64+j][d] = We[l][j][h*64+d] * 0.25
__global__ void prep_m_kernel(const float* __restrict__ We, float* __restrict__ M) {
    int idx = blockIdx.x * blockDim.x + threadIdx.x;
    if (idx >= LL * HC * HID) return;
    int d = idx & 63;
    int t = idx >> 6;
    int hj = t & 255;
    int l = t >> 8;
    int h = hj >> 6, j = hj & 63;
    M[idx] = We[l * HID * HC + j * HC + h * 64 + d] * 0.25f;
}

// ---------------- generic fp32 GEMM: C = A[Mr x K] @ B[K x Nc] (+bias)(+adds) ----------------
// BM=128 BN=64 BK=32, 256 threads, 8x4 micro-tile. K must be multiple of 32.
__global__ __launch_bounds__(256) void gemm_kernel(
    const float* __restrict__ A, const float* __restrict__ B,
    const float* __restrict__ bias,
    const float* __restrict__ add1, const float* __restrict__ add2,
    const float* __restrict__ add3,
    float* __restrict__ C, int Mr, int K, int Nc)
{
    __shared__ float As[32][129];
    __shared__ float Bs[32][64];
    int tid = threadIdx.x;
    int row0 = blockIdx.y * 128;
    int col0 = blockIdx.x * 64;
    int tx = tid & 15, ty = tid >> 4;
    float acc[8][4];
    #pragma unroll
    for (int i = 0; i < 8; i++)
        #pragma unroll
        for (int j = 0; j < 4; j++) acc[i][j] = 0.f;

    for (int k0 = 0; k0 < K; k0 += 32) {
        #pragma unroll
        for (int i = 0; i < 16; i++) {
            int m = (tid >> 5) + i * 8;
            int kk = tid & 31;
            int r = row0 + m;
            As[kk][m] = (r < Mr) ? A[(size_t)r * K + k0 + kk] : 0.f;
        }
        #pragma unroll
        for (int i = 0; i < 8; i++) {
            int kk = (tid >> 6) + i * 4;
            int nn = tid & 63;
            int c = col0 + nn;
            Bs[kk][nn] = (c < Nc) ? B[(size_t)(k0 + kk) * Nc + c] : 0.f;
        }
        __syncthreads();
        #pragma unroll
        for (int kk = 0; kk < 32; kk++) {
            float4 b4 = *reinterpret_cast<const float4*>(&Bs[kk][tx * 4]);
            #pragma unroll
            for (int i = 0; i < 8; i++) {
                float a = As[kk][ty * 8 + i];
                acc[i][0] += a * b4.x;
                acc[i][1] += a * b4.y;
                acc[i][2] += a * b4.z;
                acc[i][3] += a * b4.w;
            }
        }
        __syncthreads();
    }
    #pragma unroll
    for (int i = 0; i < 8; i++) {
        int r = row0 + ty * 8 + i;
        if (r >= Mr) continue;
        #pragma unroll
        for (int j = 0; j < 4; j++) {
            int c = col0 + tx * 4 + j;
            if (c >= Nc) continue;
            float vv = acc[i][j];
            if (bias) vv += bias[c];
            size_t o = (size_t)r * Nc + c;
            if (add1) vv += add1[o];
            if (add2) vv += add2[o];
            if (add3) vv += add3[o];
            C[o] = vv;
        }
    }
}

// ---------------- LayerNorm + ReLU (warp per row of 64) ----------------
__global__ void ln_relu_kernel(const float* __restrict__ hin, float* __restrict__ zout,
                               const float* __restrict__ g, const float* __restrict__ b, int n) {
    int gw = (blockIdx.x * blockDim.x + threadIdx.x) >> 5;
    if (gw >= n) return;
    int lane = threadIdx.x & 31;
    float x0 = hin[gw * 64 + lane];
    float x1 = hin[gw * 64 + 32 + lane];
    float s = x0 + x1;
    #pragma unroll
    for (int o = 16; o > 0; o >>= 1) s += __shfl_xor_sync(0xffffffffu, s, o);
    float mu = s * (1.f / 64.f);
    float d0 = x0 - mu, d1 = x1 - mu;
    float ss = d0 * d0 + d1 * d1;
    #pragma unroll
    for (int o = 16; o > 0; o >>= 1) ss += __shfl_xor_sync(0xffffffffu, ss, o);
    float inv = rsqrtf(ss * (1.f / 64.f) + 1e-5f);
    float z0 = fmaxf(d0 * inv * g[lane] + b[lane], 0.f);
    float z1 = fmaxf(d1 * inv * g[32 + lane] + b[32 + lane], 0.f);
    zout[gw * 64 + lane] = z0;
    zout[gw * 64 + 32 + lane] = z1;
}

// ---------------- fused per-node edge aggregation (online softmax) ----------------
// One warp per node. lane owns 8 contiguous channels ch = lane*8 .. lane*8+7,
// all belonging to head h = lane>>3. Outputs:
//   A1[i][d] = 0.25 * sum_h acc_h[d]/denom_h
//   R [i][h*64+j] = racc_h[j]/denom_h
__global__ __launch_bounds__(256) void edge_agg_kernel(
    const int* __restrict__ off, const int* __restrict__ csrc,
    const float* __restrict__ eas,
    const float* __restrict__ qb, const float* __restrict__ kb,
    const float* __restrict__ vb, const float* __restrict__ pb,
    float* __restrict__ A1, float* __restrict__ R)
{
    int gw = (blockIdx.x * blockDim.x + threadIdx.x) >> 5;
    if (gw >= NN) return;
    int lane = threadIdx.x & 31;
    int ch0 = lane << 3;
    int ealn = (lane & 7) << 3;

    float qr[8], pr[8];
    {
        float4 t0 = *reinterpret_cast<const float4*>(qb + (size_t)gw * 256 + ch0);
        float4 t1 = *reinterpret_cast<const float4*>(qb + (size_t)gw * 256 + ch0 + 4);
        qr[0]=t0.x; qr[1]=t0.y; qr[2]=t0.z; qr[3]=t0.w;
        qr[4]=t1.x; qr[5]=t1.y; qr[6]=t1.z; qr[7]=t1.w;
        float4 u0 = *reinterpret_cast<const float4*>(pb + (size_t)gw * 256 + ch0);
        float4 u1 = *reinterpret_cast<const float4*>(pb + (size_t)gw * 256 + ch0 + 4);
        pr[0]=u0.x; pr[1]=u0.y; pr[2]=u0.z; pr[3]=u0.w;
        pr[4]=u1.x; pr[5]=u1.y; pr[6]=u1.z; pr[7]=u1.w;
    }
    float m = -1e30f, den = 0.f;
    float acc[8], rac[8];
    #pragma unroll
    for (int r = 0; r < 8; r++) { acc[r] = 0.f; rac[r] = 0.f; }

    int beg = off[gw], end = off[gw + 1];
    for (int epos = beg; epos < end; epos++) {
        int src = csrc[epos];
        const float* kp = kb + (size_t)src * 256 + ch0;
        float4 k0 = *reinterpret_cast<const float4*>(kp);
        float4 k1 = *reinterpret_cast<const float4*>(kp + 4);
        const float* ep = eas + (size_t)epos * 64 + ealn;
        float4 e0 = *reinterpret_cast<const float4*>(ep);
        float4 e1 = *reinterpret_cast<const float4*>(ep + 4);
        const float* vp = vb + (size_t)src * 256 + ch0;
        float4 v0 = *reinterpret_cast<const float4*>(vp);
        float4 v1 = *reinterpret_cast<const float4*>(vp + 4);

        float s = qr[0]*k0.x + qr[1]*k0.y + qr[2]*k0.z + qr[3]*k0.w
                + qr[4]*k1.x + qr[5]*k1.y + qr[6]*k1.z + qr[7]*k1.w
                + pr[0]*e0.x + pr[1]*e0.y + pr[2]*e0.z + pr[3]*e0.w
                + pr[4]*e1.x + pr[5]*e1.y + pr[6]*e1.z + pr[7]*e1.w;
        // reduce over the 8 lanes of this head
        s += __shfl_xor_sync(0xffffffffu, s, 1, 8);
        s += __shfl_xor_sync(0xffffffffu, s, 2, 8);
        s += __shfl_xor_sync(0xffffffffu, s, 4, 8);
        float alpha = s * 0.125f;

        float mn = fmaxf(m, alpha);
        float sc = __expf(m - mn);       // 0 on first edge (m=-1e30)
        float w  = __expf(alpha - mn);
        m = mn;
        den = den * sc + w;
        acc[0] = acc[0]*sc + w*v0.x;  acc[1] = acc[1]*sc + w*v0.y;
        acc[2] = acc[2]*sc + w*v0.z;  acc[3] = acc[3]*sc + w*v0.w;
        acc[4] = acc[4]*sc + w*v1.x;  acc[5] = acc[5]*sc + w*v1.y;
        acc[6] = acc[6]*sc + w*v1.z;  acc[7] = acc[7]*sc + w*v1.w;
        rac[0] = rac[0]*sc + w*e0.x;  rac[1] = rac[1]*sc + w*e0.y;
        rac[2] = rac[2]*sc + w*e0.z;  rac[3] = rac[3]*sc + w*e0.w;
        rac[4] = rac[4]*sc + w*e1.x;  rac[5] = rac[5]*sc + w*e1.y;
        rac[6] = rac[6]*sc + w*e1.z;  rac[7] = rac[7]*sc + w*e1.w;
    }
    float dinv = 1.f / (den + 1e-16f);
    float a1[8];
    #pragma unroll
    for (int r = 0; r < 8; r++) a1[r] = acc[r] * dinv * 0.25f;
    #pragma unroll
    for (int r = 0; r < 8; r++) {
        a1[r] += __shfl_xor_sync(0xffffffffu, a1[r], 8);
        a1[r] += __shfl_xor_sync(0xffffffffu, a1[r], 16);
    }
    if (lane < 8) {
        float4 o0 = make_float4(a1[0], a1[1], a1[2], a1[3]);
        float4 o1 = make_float4(a1[4], a1[5], a1[6], a1[7]);
        *reinterpret_cast<float4*>(A1 + (size_t)gw * 64 + ealn)     = o0;
        *reinterpret_cast<float4*>(A1 + (size_t)gw * 64 + ealn + 4) = o1;
    }
    #pragma unroll
    for (int r = 0; r < 8; r++) rac[r] *= dinv;
    float4 r0 = make_float4(rac[0], rac[1], rac[2], rac[3]);
    float4 r1 = make_float4(rac[4], rac[5], rac[6], rac[7]);
    *reinterpret_cast<float4*>(R + (size_t)gw * 256 + ch0)     = r0;
    *reinterpret_cast<float4*>(R + (size_t)gw * 256 + ch0 + 4) = r1;
}

// ---------------- host launch ----------------
extern "C" void kernel_launch(void* const* d_in, const int* in_sizes, int n_in,
                              void* d_out, int out_size) {
    const float* x         = (const float*)d_in[0];
    const int*   ei        = (const int*)  d_in[1];
    const float* edge_attr = (const float*)d_in[2];
    const float* node_W    = (const float*)d_in[3];
    const float* node_b    = (const float*)d_in[4];
    const float* eenc_W    = (const float*)d_in[5];
    const float* eenc_b    = (const float*)d_in[6];
    const float* Wq        = (const float*)d_in[7];
    const float* bq        = (const float*)d_in[8];
    const float* Wk        = (const float*)d_in[9];
    const float* bk        = (const float*)d_in[10];
    const float* Wv        = (const float*)d_in[11];
    const float* bv        = (const float*)d_in[12];
    const float* We        = (const float*)d_in[13];
    const float* Wskip     = (const float*)d_in[14];
    const float* bskip     = (const float*)d_in[15];
    const float* ln_g      = (const float*)d_in[16];
    const float* ln_b      = (const float*)d_in[17];
    const float* lin_W     = (const float*)d_in[18];
    const float* lin_b     = (const float*)d_in[19];
    float* out = (float*)d_out;

    float *h_, *z_, *skip_, *A1_, *q_, *k_, *v_, *p_, *R_, *ea_, *eas_, *Wp_, *bp_, *M_;
    int *deg_, *off_, *cur_, *csrc_, *ceid_;
    cudaGetSymbolAddress((void**)&h_,    g_h);
    cudaGetSymbolAddress((void**)&z_,    g_z);
    cudaGetSymbolAddress((void**)&skip_, g_skip);
    cudaGetSymbolAddress((void**)&A1_,   g_A1);
    cudaGetSymbolAddress((void**)&q_,    g_q);
    cudaGetSymbolAddress((void**)&k_,    g_k);
    cudaGetSymbolAddress((void**)&v_,    g_v);
    cudaGetSymbolAddress((void**)&p_,    g_p);
    cudaGetSymbolAddress((void**)&R_,    g_R);
    cudaGetSymbolAddress((void**)&ea_,   g_ea);
    cudaGetSymbolAddress((void**)&eas_,  g_eas);
    cudaGetSymbolAddress((void**)&Wp_,   g_Wp);
    cudaGetSymbolAddress((void**)&bp_,   g_bp);
    cudaGetSymbolAddress((void**)&M_,    g_M);
    cudaGetSymbolAddress((void**)&deg_,  g_deg);
    cudaGetSymbolAddress((void**)&off_,  g_off);
    cudaGetSymbolAddress((void**)&cur_,  g_cur);
    cudaGetSymbolAddress((void**)&csrc_, g_csrc);
    cudaGetSymbolAddress((void**)&ceid_, g_ceid);

    const int rowsN = (NN + 127) / 128;   // 157
    const int rowsE = (EE + 127) / 128;   // 2500

    // CSR build
    zero_int_kernel<<<(NN + 255) / 256, 256>>>(deg_, NN);
    hist_kernel<<<(EE + 255) / 256, 256>>>(ei, deg_, EE);
    scan_kernel<<<1, 1024>>>(deg_, off_, cur_, NN, EE);
    scatter_kernel<<<(EE + 255) / 256, 256>>>(ei, cur_, csrc_, ceid_, EE);

    // encoders
    gemm_kernel<<<dim3(1, rowsE), 256>>>(edge_attr, eenc_W, eenc_b,
                                         nullptr, nullptr, nullptr, ea_, EE, 64, 64);
    permute_ea_kernel<<<(EE * 16 + 255) / 256, 256>>>(ea_, ceid_, eas_, EE);
    gemm_kernel<<<dim3(1, rowsN), 256>>>(x, node_W, node_b,
                                         nullptr, nullptr, nullptr, h_, NN, 128, 64);

    // folded weights
    prep_wp_kernel<<<(LL * 65 * HC + 255) / 256, 256>>>(Wq, bq, We, Wp_, bp_);
    prep_m_kernel<<<(LL * HC * HID + 255) / 256, 256>>>(We, M_);

    for (int l = 0; l < LL; l++) {
        const float* zin;
        if (l == 0) {
            zin = h_;
        } else {
            ln_relu_kernel<<<(NN * 32 + 255) / 256, 256>>>(h_, z_, ln_g + l * 64, ln_b + l * 64, NN);
            zin = z_;
        }
        gemm_kernel<<<dim3(4, rowsN), 256>>>(zin, Wq + l * HID * HC, bq + l * HC,
                                             nullptr, nullptr, nullptr, q_, NN, 64, 256);
        gemm_kernel<<<dim3(4, rowsN), 256>>>(zin, Wk + l * HID * HC, bk + l * HC,
                                             nullptr, nullptr, nullptr, k_, NN, 64, 256);
        gemm_kernel<<<dim3(4, rowsN), 256>>>(zin, Wv + l * HID * HC, bv + l * HC,
                                             nullptr, nullptr, nullptr, v_, NN, 64, 256);
        gemm_kernel<<<dim3(4, rowsN), 256>>>(zin, Wp_ + l * HID * HC, bp_ + l * HC,
                                             nullptr, nullptr, nullptr, p_, NN, 64, 256);
        gemm_kernel<<<dim3(1, rowsN), 256>>>(zin, Wskip + l * HID * HID, bskip + l * HID,
                                             nullptr, nullptr, nullptr, skip_, NN, 64, 64);
        edge_agg_kernel<<<(NN * 32) / 256, 256>>>(off_, csrc_, eas_, q_, k_, v_, p_, A1_, R_);
        // h = R@M + A1 + skip (+ h residual for l>0)
        gemm_kernel<<<dim3(1, rowsN), 256>>>(R_, M_ + l * HC * HID, nullptr,
                                             A1_, skip_, (l > 0 ? h_ : nullptr),
                                             h_, NN, 256, 64);
    }

    // final LN(g[0],b[0]) + relu + linear head
    ln_relu_kernel<<<(NN * 32 + 255) / 256, 256>>>(h_, z_, ln_g, ln_b, NN);
    gemm_kernel<<<dim3(1, rowsN), 256>>>(z_, lin_W, lin_b,
                                         nullptr, nullptr, nullptr, out, NN, 64, 32);
}

// round 5
// speedup vs baseline: 1.3496x; 1.3496x over previous
#include <cuda_runtime.h>
#include <cuda_bf16.h>
#include <cstdint>

// Problem constants
#define NN   20000
#define EE   320000
#define FIN  128
#define HID  64
#define HC   256   // H*C
#define LL   4
#define NCOMB 1088 // q(256)|k(256)|v(256)|p(256)|skip(64)

// ---------------- scratch (device globals; no allocation allowed) ----------------
__device__ __align__(16) float g_h   [NN*HID];
__device__ __align__(16) float g_z   [NN*HID];
__device__ __align__(16) float g_A1  [NN*HID];
__device__ __align__(16) float g_qkvp[NN*NCOMB];
__device__ __align__(16) float g_R   [NN*HC];
__device__ __align__(16) float g_eas [EE*HID];
__device__ __align__(16) float g_Wc  [LL*HID*NCOMB];
__device__ __align__(16) float g_bc  [LL*NCOMB];
__device__ __align__(16) float g_M   [LL*HC*HID];
__device__ int g_deg [NN];
__device__ int g_off [NN+1];
__device__ int g_cur [NN];
__device__ int g_csrc[EE];
__device__ int g_ceid[EE];

// ---------------- small utility kernels ----------------
__global__ void zero_int_kernel(int* p, int n) {
    int i = blockIdx.x * blockDim.x + threadIdx.x;
    if (i < n) p[i] = 0;
}

__global__ void hist_kernel(const int* __restrict__ ei, int* __restrict__ deg, int E) {
    int e = blockIdx.x * blockDim.x + threadIdx.x;
    if (e < E) atomicAdd(&deg[ei[E + e]], 1);
}

// single-block exclusive scan of deg -> off, cur
__global__ void scan_kernel(const int* __restrict__ deg, int* __restrict__ off,
                            int* __restrict__ cur, int n, int total) {
    const int T = 1024;
    int tid = threadIdx.x;
    int chunk = (n + T - 1) / T;
    int s = tid * chunk;
    int e = s + chunk; if (e > n) e = n;
    int local = 0;
    for (int i = s; i < e; i++) local += deg[i];
    int lane = tid & 31, w = tid >> 5;
    int v = local;
    #pragma unroll
    for (int o = 1; o < 32; o <<= 1) {
        int t2 = __shfl_up_sync(0xffffffffu, v, o);
        if (lane >= o) v += t2;
    }
    __shared__ int wsum[32];
    if (lane == 31) wsum[w] = v;
    __syncthreads();
    if (w == 0) {
        int x = wsum[lane];
        #pragma unroll
        for (int o = 1; o < 32; o <<= 1) {
            int t2 = __shfl_up_sync(0xffffffffu, x, o);
            if (lane >= o) x += t2;
        }
        wsum[lane] = x;
    }
    __syncthreads();
    int incl = v + (w > 0 ? wsum[w - 1] : 0);
    int p = incl - local;
    for (int i = s; i < e; i++) { off[i] = p; cur[i] = p; p += deg[i]; }
    if (tid == 0) off[n] = total;
}

__global__ void scatter_kernel(const int* __restrict__ ei, int* __restrict__ cur,
                               int* __restrict__ csrc, int* __restrict__ ceid, int E) {
    int e = blockIdx.x * blockDim.x + threadIdx.x;
    if (e >= E) return;
    int s = ei[e];
    int d = ei[E + e];
    int pos = atomicAdd(&cur[d], 1);
    csrc[pos] = s;
    ceid[pos] = e;
}

// ---------------- weight prep: combined [64 x 1088] + bias ----------------
// cols 0..255 Wq/bq | 256..511 Wk/bk | 512..767 Wv/bv |
// 768..1023 Wp fold: Wp[f][h*64+j] = sum_c WqRow[h*64+c]*We[l][j][h*64+c] |
// 1024..1087 Wskip/bskip
__global__ void prep_comb_kernel(const float* __restrict__ Wq, const float* __restrict__ bq,
                                 const float* __restrict__ Wk, const float* __restrict__ bk,
                                 const float* __restrict__ Wv, const float* __restrict__ bv,
                                 const float* __restrict__ We,
                                 const float* __restrict__ Wskip, const float* __restrict__ bskip,
                                 float* __restrict__ Wc, float* __restrict__ bc) {
    int idx = blockIdx.x * blockDim.x + threadIdx.x;
    if (idx >= LL * 65 * NCOMB) return;
    int col = idx % NCOMB;
    int t = idx / NCOMB;
    int f = t % 65;       // 64 == bias row
    int l = t / 65;
    float val;
    if (col < 256) {
        val = (f < 64) ? Wq[l * HID * HC + f * HC + col] : bq[l * HC + col];
    } else if (col < 512) {
        int c = col - 256;
        val = (f < 64) ? Wk[l * HID * HC + f * HC + c] : bk[l * HC + c];
    } else if (col < 768) {
        int c = col - 512;
        val = (f < 64) ? Wv[l * HID * HC + f * HC + c] : bv[l * HC + c];
    } else if (col < 1024) {
        int hj = col - 768;
        int h = hj >> 6, j = hj & 63;
        const float* arow = (f < 64) ? (Wq + l * HID * HC + f * HC) : (bq + l * HC);
        const float* wrow = We + l * HID * HC + j * HC;
        float s = 0.f;
        #pragma unroll 8
        for (int c = 0; c < 64; c++) s += arow[h * 64 + c] * wrow[h * 64 + c];
        val = s;
    } else {
        int c = col - 1024;
        val = (f < 64) ? Wskip[l * HID * HID + f * HID + c] : bskip[l * HID + c];
    }
    if (f < 64) Wc[l * HID * NCOMB + f * NCOMB + col] = val;
    else        bc[l * NCOMB + col] = val;
}

// M[l][h*64+j][d] = We[l][j][h*64+d] * 0.25
__global__ void prep_m_kernel(const float* __restrict__ We, float* __restrict__ M) {
    int idx = blockIdx.x * blockDim.x + threadIdx.x;
    if (idx >= LL * HC * HID) return;
    int d = idx & 63;
    int t = idx >> 6;
    int hj = t & 255;
    int l = t >> 8;
    int h = hj >> 6, j = hj & 63;
    M[idx] = We[l * HID * HC + j * HC + h * 64 + d] * 0.25f;
}

// ---------------- tf32 tensor-core GEMM ----------------
// C[Mr x Nc] = A[Mr x K] @ B[K x Nc] (+bias)(+add1*s1)(+add2*s2)(+add3*s3)
// Optional rowmap: A row index indirection (gather GEMM).
// BM=128 BN=64 BK=32, 256 threads = 8 warps (4x2), warp tile 32x32,
// mma.sync.aligned.m16n8k8 tf32. K must be a multiple of 32, Nc a multiple of 32.
__device__ __forceinline__ float tf32r(float x) {
    uint32_t u;
    asm("cvt.rna.tf32.f32 %0, %1;" : "=r"(u) : "f"(x));
    return __uint_as_float(u);
}
__device__ __forceinline__ void mma_tf32(float* d, const uint32_t* a, const uint32_t* b) {
    asm volatile("mma.sync.aligned.m16n8k8.row.col.f32.tf32.tf32.f32 "
        "{%0,%1,%2,%3}, {%4,%5,%6,%7}, {%8,%9}, {%0,%1,%2,%3};"
        : "+f"(d[0]), "+f"(d[1]), "+f"(d[2]), "+f"(d[3])
        : "r"(a[0]), "r"(a[1]), "r"(a[2]), "r"(a[3]), "r"(b[0]), "r"(b[1]));
}

__global__ __launch_bounds__(256) void gemm_tf32_kernel(
    const float* __restrict__ A, const int* __restrict__ rowmap,
    const float* __restrict__ B, const float* __restrict__ bias,
    const float* __restrict__ add1, int s1,
    const float* __restrict__ add2, int s2,
    const float* __restrict__ add3, int s3,
    float* __restrict__ C, int Mr, int K, int Nc)
{
    __shared__ float As[128][36];  // stride 36: conflict-free frag loads, 16B-aligned f4 stores
    __shared__ float Bs[32][72];   // stride 72: conflict-free frag loads
    int tid = threadIdx.x;
    int warp = tid >> 5, lane = tid & 31;
    int wm = warp >> 1;            // 0..3
    int wn = warp & 1;             // 0..1
    int grp = lane >> 2, tg = lane & 3;
    int row0 = blockIdx.y * 128;
    int col0 = blockIdx.x * 64;

    float acc[2][4][4];
    #pragma unroll
    for (int mi = 0; mi < 2; mi++)
        #pragma unroll
        for (int ni = 0; ni < 4; ni++)
            #pragma unroll
            for (int r = 0; r < 4; r++) acc[mi][ni][r] = 0.f;

    for (int k0 = 0; k0 < K; k0 += 32) {
        #pragma unroll
        for (int j = 0; j < 4; j++) {
            int idx = tid + j * 256;
            int r = idx >> 3;
            int c = (idx & 7) << 2;
            int gr = row0 + r;
            float4 av = make_float4(0.f, 0.f, 0.f, 0.f);
            if (gr < Mr) {
                int grr = rowmap ? __ldg(rowmap + gr) : gr;
                av = *reinterpret_cast<const float4*>(A + (size_t)grr * K + k0 + c);
            }
            av.x = tf32r(av.x); av.y = tf32r(av.y);
            av.z = tf32r(av.z); av.w = tf32r(av.w);
            *reinterpret_cast<float4*>(&As[r][c]) = av;
        }
        #pragma unroll
        for (int j = 0; j < 2; j++) {
            int idx = tid + j * 256;
            int r = idx >> 4;
            int c = (idx & 15) << 2;
            int gc = col0 + c;
            float4 bv = make_float4(0.f, 0.f, 0.f, 0.f);
            if (gc < Nc)
                bv = *reinterpret_cast<const float4*>(B + (size_t)(k0 + r) * Nc + gc);
            bv.x = tf32r(bv.x); bv.y = tf32r(bv.y);
            bv.z = tf32r(bv.z); bv.w = tf32r(bv.w);
            *reinterpret_cast<float4*>(&Bs[r][c]) = bv;
        }
        __syncthreads();
        #pragma unroll
        for (int kk = 0; kk < 32; kk += 8) {
            uint32_t a[2][4], b[4][2];
            int ar = wm * 32 + grp;
            #pragma unroll
            for (int mi = 0; mi < 2; mi++) {
                a[mi][0] = __float_as_uint(As[ar + mi * 16][kk + tg]);
                a[mi][1] = __float_as_uint(As[ar + mi * 16 + 8][kk + tg]);
                a[mi][2] = __float_as_uint(As[ar + mi * 16][kk + tg + 4]);
                a[mi][3] = __float_as_uint(As[ar + mi * 16 + 8][kk + tg + 4]);
            }
            #pragma unroll
            for (int ni = 0; ni < 4; ni++) {
                int bcn = wn * 32 + ni * 8 + grp;
                b[ni][0] = __float_as_uint(Bs[kk + tg][bcn]);
                b[ni][1] = __float_as_uint(Bs[kk + tg + 4][bcn]);
            }
            #pragma unroll
            for (int mi = 0; mi < 2; mi++)
                #pragma unroll
                for (int ni = 0; ni < 4; ni++)
                    mma_tf32(acc[mi][ni], a[mi], b[ni]);
        }
        __syncthreads();
    }

    // epilogue
    #pragma unroll
    for (int mi = 0; mi < 2; mi++) {
        int r0 = row0 + wm * 32 + mi * 16 + grp;
        #pragma unroll
        for (int ni = 0; ni < 4; ni++) {
            int c = col0 + wn * 32 + ni * 8 + tg * 2;
            if (c >= Nc) continue;
            #pragma unroll
            for (int half = 0; half < 2; half++) {
                int r = r0 + half * 8;
                if (r >= Mr) continue;
                #pragma unroll
                for (int jj = 0; jj < 2; jj++) {
                    float vv = acc[mi][ni][half * 2 + jj];
                    int cc = c + jj;
                    if (bias) vv += bias[cc];
                    if (add1) vv += add1[(size_t)r * s1 + cc];
                    if (add2) vv += add2[(size_t)r * s2 + cc];
                    if (add3) vv += add3[(size_t)r * s3 + cc];
                    C[(size_t)r * Nc + cc] = vv;
                }
            }
        }
    }
}

// ---------------- LayerNorm + ReLU (warp per row of 64) ----------------
__global__ void ln_relu_kernel(const float* __restrict__ hin, float* __restrict__ zout,
                               const float* __restrict__ g, const float* __restrict__ b, int n) {
    int gw = (blockIdx.x * blockDim.x + threadIdx.x) >> 5;
    if (gw >= n) return;
    int lane = threadIdx.x & 31;
    float x0 = hin[gw * 64 + lane];
    float x1 = hin[gw * 64 + 32 + lane];
    float s = x0 + x1;
    #pragma unroll
    for (int o = 16; o > 0; o >>= 1) s += __shfl_xor_sync(0xffffffffu, s, o);
    float mu = s * (1.f / 64.f);
    float d0 = x0 - mu, d1 = x1 - mu;
    float ss = d0 * d0 + d1 * d1;
    #pragma unroll
    for (int o = 16; o > 0; o >>= 1) ss += __shfl_xor_sync(0xffffffffu, ss, o);
    float inv = rsqrtf(ss * (1.f / 64.f) + 1e-5f);
    float z0 = fmaxf(d0 * inv * g[lane] + b[lane], 0.f);
    float z1 = fmaxf(d1 * inv * g[32 + lane] + b[32 + lane], 0.f);
    zout[gw * 64 + lane] = z0;
    zout[gw * 64 + 32 + lane] = z1;
}

// ---------------- fused per-node edge aggregation (online softmax) ----------------
// One warp per node; lane owns channels ch0=lane*8 (head h=lane>>3).
// qkvp combined buffer stride NCOMB: q@0, k@256, v@512, p@768.
__global__ __launch_bounds__(256) void edge_agg_kernel(
    const int* __restrict__ off, const int* __restrict__ csrc,
    const float* __restrict__ eas, const float* __restrict__ qkvp,
    float* __restrict__ A1, float* __restrict__ R)
{
    int gw = (blockIdx.x * blockDim.x + threadIdx.x) >> 5;
    if (gw >= NN) return;
    int lane = threadIdx.x & 31;
    int ch0 = lane << 3;
    int ealn = (lane & 7) << 3;

    float qr[8], pr[8];
    {
        const float* qp = qkvp + (size_t)gw * NCOMB + ch0;
        float4 t0 = *reinterpret_cast<const float4*>(qp);
        float4 t1 = *reinterpret_cast<const float4*>(qp + 4);
        qr[0]=t0.x; qr[1]=t0.y; qr[2]=t0.z; qr[3]=t0.w;
        qr[4]=t1.x; qr[5]=t1.y; qr[6]=t1.z; qr[7]=t1.w;
        float4 u0 = *reinterpret_cast<const float4*>(qp + 768);
        float4 u1 = *reinterpret_cast<const float4*>(qp + 772);
        pr[0]=u0.x; pr[1]=u0.y; pr[2]=u0.z; pr[3]=u0.w;
        pr[4]=u1.x; pr[5]=u1.y; pr[6]=u1.z; pr[7]=u1.w;
    }
    float m = -1e30f, den = 0.f;
    float acc[8], rac[8];
    #pragma unroll
    for (int r = 0; r < 8; r++) { acc[r] = 0.f; rac[r] = 0.f; }

    int beg = off[gw], end = off[gw + 1];
    #pragma unroll 2
    for (int epos = beg; epos < end; epos++) {
        int src = csrc[epos];
        const float* kp = qkvp + (size_t)src * NCOMB + 256 + ch0;
        float4 k0 = *reinterpret_cast<const float4*>(kp);
        float4 k1 = *reinterpret_cast<const float4*>(kp + 4);
        const float* ep = eas + (size_t)epos * 64 + ealn;
        float4 e0 = *reinterpret_cast<const float4*>(ep);
        float4 e1 = *reinterpret_cast<const float4*>(ep + 4);
        float4 v0 = *reinterpret_cast<const float4*>(kp + 256);
        float4 v1 = *reinterpret_cast<const float4*>(kp + 260);

        float s = qr[0]*k0.x + qr[1]*k0.y + qr[2]*k0.z + qr[3]*k0.w
                + qr[4]*k1.x + qr[5]*k1.y + qr[6]*k1.z + qr[7]*k1.w
                + pr[0]*e0.x + pr[1]*e0.y + pr[2]*e0.z + pr[3]*e0.w
                + pr[4]*e1.x + pr[5]*e1.y + pr[6]*e1.z + pr[7]*e1.w;
        s += __shfl_xor_sync(0xffffffffu, s, 1, 8);
        s += __shfl_xor_sync(0xffffffffu, s, 2, 8);
        s += __shfl_xor_sync(0xffffffffu, s, 4, 8);
        float alpha = s * 0.125f;

        float mn = fmaxf(m, alpha);
        float sc = __expf(m - mn);
        float w  = __expf(alpha - mn);
        m = mn;
        den = den * sc + w;
        acc[0] = acc[0]*sc + w*v0.x;  acc[1] = acc[1]*sc + w*v0.y;
        acc[2] = acc[2]*sc + w*v0.z;  acc[3] = acc[3]*sc + w*v0.w;
        acc[4] = acc[4]*sc + w*v1.x;  acc[5] = acc[5]*sc + w*v1.y;
        acc[6] = acc[6]*sc + w*v1.z;  acc[7] = acc[7]*sc + w*v1.w;
        rac[0] = rac[0]*sc + w*e0.x;  rac[1] = rac[1]*sc + w*e0.y;
        rac[2] = rac[2]*sc + w*e0.z;  rac[3] = rac[3]*sc + w*e0.w;
        rac[4] = rac[4]*sc + w*e1.x;  rac[5] = rac[5]*sc + w*e1.y;
        rac[6] = rac[6]*sc + w*e1.z;  rac[7] = rac[7]*sc + w*e1.w;
    }
    float dinv = 1.f / (den + 1e-16f);
    float a1[8];
    #pragma unroll
    for (int r = 0; r < 8; r++) a1[r] = acc[r] * dinv * 0.25f;
    #pragma unroll
    for (int r = 0; r < 8; r++) {
        a1[r] += __shfl_xor_sync(0xffffffffu, a1[r], 8);
        a1[r] += __shfl_xor_sync(0xffffffffu, a1[r], 16);
    }
    if (lane < 8) {
        *reinterpret_cast<float4*>(A1 + (size_t)gw * 64 + ealn) =
            make_float4(a1[0], a1[1], a1[2], a1[3]);
        *reinterpret_cast<float4*>(A1 + (size_t)gw * 64 + ealn + 4) =
            make_float4(a1[4], a1[5], a1[6], a1[7]);
    }
    #pragma unroll
    for (int r = 0; r < 8; r++) rac[r] *= dinv;
    *reinterpret_cast<float4*>(R + (size_t)gw * 256 + ch0) =
        make_float4(rac[0], rac[1], rac[2], rac[3]);
    *reinterpret_cast<float4*>(R + (size_t)gw * 256 + ch0 + 4) =
        make_float4(rac[4], rac[5], rac[6], rac[7]);
}

// ---------------- host launch ----------------
static inline void gemm(const float* A, const int* rowmap, const float* B, const float* bias,
                        const float* a1, int s1, const float* a2, int s2,
                        const float* a3, int s3,
                        float* C, int Mr, int K, int Nc) {
    dim3 grid((Nc + 63) / 64, (Mr + 127) / 128);
    gemm_tf32_kernel<<<grid, 256>>>(A, rowmap, B, bias, a1, s1, a2, s2, a3, s3, C, Mr, K, Nc);
}

extern "C" void kernel_launch(void* const* d_in, const int* in_sizes, int n_in,
                              void* d_out, int out_size) {
    const float* x         = (const float*)d_in[0];
    const int*   ei        = (const int*)  d_in[1];
    const float* edge_attr = (const float*)d_in[2];
    const float* node_W    = (const float*)d_in[3];
    const float* node_b    = (const float*)d_in[4];
    const float* eenc_W    = (const float*)d_in[5];
    const float* eenc_b    = (const float*)d_in[6];
    const float* Wq        = (const float*)d_in[7];
    const float* bq        = (const float*)d_in[8];
    const float* Wk        = (const float*)d_in[9];
    const float* bk        = (const float*)d_in[10];
    const float* Wv        = (const float*)d_in[11];
    const float* bv        = (const float*)d_in[12];
    const float* We        = (const float*)d_in[13];
    const float* Wskip     = (const float*)d_in[14];
    const float* bskip     = (const float*)d_in[15];
    const float* ln_g      = (const float*)d_in[16];
    const float* ln_b      = (const float*)d_in[17];
    const float* lin_W     = (const float*)d_in[18];
    const float* lin_b     = (const float*)d_in[19];
    float* out = (float*)d_out;

    float *h_, *z_, *A1_, *qkvp_, *R_, *eas_, *Wc_, *bc_, *M_;
    int *deg_, *off_, *cur_, *csrc_, *ceid_;
    cudaGetSymbolAddress((void**)&h_,    g_h);
    cudaGetSymbolAddress((void**)&z_,    g_z);
    cudaGetSymbolAddress((void**)&A1_,   g_A1);
    cudaGetSymbolAddress((void**)&qkvp_, g_qkvp);
    cudaGetSymbolAddress((void**)&R_,    g_R);
    cudaGetSymbolAddress((void**)&eas_,  g_eas);
    cudaGetSymbolAddress((void**)&Wc_,   g_Wc);
    cudaGetSymbolAddress((void**)&bc_,   g_bc);
    cudaGetSymbolAddress((void**)&M_,    g_M);
    cudaGetSymbolAddress((void**)&deg_,  g_deg);
    cudaGetSymbolAddress((void**)&off_,  g_off);
    cudaGetSymbolAddress((void**)&cur_,  g_cur);
    cudaGetSymbolAddress((void**)&csrc_, g_csrc);
    cudaGetSymbolAddress((void**)&ceid_, g_ceid);

    // CSR build
    zero_int_kernel<<<(NN + 255) / 256, 256>>>(deg_, NN);
    hist_kernel<<<(EE + 255) / 256, 256>>>(ei, deg_, EE);
    scan_kernel<<<1, 1024>>>(deg_, off_, cur_, NN, EE);
    scatter_kernel<<<(EE + 255) / 256, 256>>>(ei, cur_, csrc_, ceid_, EE);

    // folded/combined weights
    prep_comb_kernel<<<(LL * 65 * NCOMB + 255) / 256, 256>>>(
        Wq, bq, Wk, bk, Wv, bv, We, Wskip, bskip, Wc_, bc_);
    prep_m_kernel<<<(LL * HC * HID + 255) / 256, 256>>>(We, M_);

    // encoders: edge encoder gathers rows in CSR order directly (rowmap=ceid)
    gemm(edge_attr, ceid_, eenc_W, eenc_b, nullptr, 0, nullptr, 0, nullptr, 0,
         eas_, EE, 64, 64);
    gemm(x, nullptr, node_W, node_b, nullptr, 0, nullptr, 0, nullptr, 0,
         h_, NN, 128, 64);

    for (int l = 0; l < LL; l++) {
        const float* zin;
        if (l == 0) {
            zin = h_;
        } else {
            ln_relu_kernel<<<(NN * 32 + 255) / 256, 256>>>(h_, z_, ln_g + l * 64, ln_b + l * 64, NN);
            zin = z_;
        }
        // one fused GEMM: [q|k|v|p|skip]
        gemm(zin, nullptr, Wc_ + l * HID * NCOMB, bc_ + l * NCOMB,
             nullptr, 0, nullptr, 0, nullptr, 0, qkvp_, NN, 64, NCOMB);
        edge_agg_kernel<<<(NN * 32) / 256, 256>>>(off_, csrc_, eas_, qkvp_, A1_, R_);
        // h = R@M + A1 + skip (+ h residual for l>0)
        gemm(R_, nullptr, M_ + l * HC * HID, nullptr,
             A1_, 64, qkvp_ + 1024, NCOMB, (l > 0 ? h_ : nullptr), 64,
             h_, NN, 256, 64);
    }

    // final LN(g[0],b[0]) + relu + linear head
    ln_relu_kernel<<<(NN * 32 + 255) / 256, 256>>>(h_, z_, ln_g, ln_b, NN);
    gemm(z_, nullptr, lin_W, lin_b, nullptr, 0, nullptr, 0, nullptr, 0,
         out, NN, 64, 32);
}